// round 12
// baseline (speedup 1.0000x reference)
#include <cuda_runtime.h>

#define N_TOK   8192
#define E_EXP   8
#define DIM     2048
#define OUT_ROWS (N_TOK * 2)              // 16384
#define TAGS_OFF ((size_t)OUT_ROWS * DIM) // 33554432
#define CNT_OFF  (TAGS_OFF + OUT_ROWS)
#define NBLK    1024                      // persistent blocks, 8 tokens each
#define TPB     8

// scratch (no device allocs allowed)
__device__ unsigned int g_pcnt[NBLK];  // nibble-packed per-block expert counts
__device__ unsigned int g_sync;        // monotonic ticket barrier (replay-safe)

__device__ __forceinline__ unsigned long long expand_lo(unsigned int p) {
    return (unsigned long long)(p & 0xF)
         | ((unsigned long long)((p >>  4) & 0xF) << 16)
         | ((unsigned long long)((p >>  8) & 0xF) << 32)
         | ((unsigned long long)((p >> 12) & 0xF) << 48);
}
__device__ __forceinline__ unsigned long long expand_hi(unsigned int p) {
    return expand_lo(p >> 16);
}
__device__ __forceinline__ int fld(unsigned long long v, int e) {
    return (int)((v >> (16 * e)) & 0xFFFF);
}

__global__ __launch_bounds__(256, 8) void fused_kernel(
    const float4* __restrict__ gates4,
    const float4* __restrict__ in_flow,
    float4* __restrict__ out4,
    float* __restrict__ out)
{
    __shared__ unsigned int       s_mask[TPB];
    __shared__ int2               s_dst[TPB];
    __shared__ unsigned long long s_red[8][4];

    const int b = blockIdx.x;
    const int t = threadIdx.x;
    const int lane = t & 31, w = t >> 5;

    // ───── Phase 1: route this block's 8 tokens (threads 0..7) ─────
    unsigned int pack = 0;
    if (t < TPB) {
        const int n = b * TPB + t;
        const float4 a  = __ldg(gates4 + (size_t)n * 2);
        const float4 b4 = __ldg(gates4 + (size_t)n * 2 + 1);
        float g[E_EXP] = {a.x, a.y, a.z, a.w, b4.x, b4.y, b4.z, b4.w};

        int e1 = 0; float v1 = g[0];
        #pragma unroll
        for (int e = 1; e < E_EXP; e++) if (g[e] > v1) { v1 = g[e]; e1 = e; }
        int e2 = (e1 == 0) ? 1 : 0; float v2 = g[e2];
        #pragma unroll
        for (int e = 0; e < E_EXP; e++)
            if (e != e1 && g[e] > v2) { v2 = g[e]; e2 = e; }
        const unsigned int mb = (1u << e1) | (1u << e2);
        s_mask[t] = mb;
        #pragma unroll
        for (int e = 0; e < E_EXP; e++) pack |= ((mb >> e) & 1u) << (4 * e);
    }
    if (w == 0) {
        #pragma unroll
        for (int off = 4; off > 0; off >>= 1)
            pack += __shfl_down_sync(0xFFFFFFFFu, pack, off);
        if (lane == 0) g_pcnt[b] = pack;   // plain store (L2-visible after fence)
    }

    // ───── prefetch this block's in_flow rows into L2 (overlaps routing) ───
    {
        const char* base = (const char*)(in_flow + (size_t)b * TPB * (DIM / 4));
        asm volatile("prefetch.global.L2 [%0];" :: "l"(base + (size_t)t * 128));
        asm volatile("prefetch.global.L2 [%0];" :: "l"(base + (size_t)(t + 256) * 128));
    }

    // ───── device-wide ticket barrier (all 1024 blocks resident) ─────
    __syncthreads();
    if (t == 0) {
        __threadfence();
        const unsigned int ticket = atomicAdd(&g_sync, 1u);
        const unsigned int target = (ticket / NBLK + 1u) * NBLK;
        volatile unsigned int* sy = &g_sync;
        while (*sy < target) { }
        __threadfence();
    }
    __syncthreads();

    // ───── Phase 2: totals + prefix over earlier blocks (4KB, coherent L2) ─
    unsigned long long tlo = 0ull, thi = 0ull, plo = 0ull, phi = 0ull;
    #pragma unroll
    for (int i = t; i < NBLK; i += 256) {
        const unsigned int p = __ldcg(&g_pcnt[i]);   // L2-coherent, bypass L1
        const unsigned long long lo = expand_lo(p);
        const unsigned long long hi = expand_hi(p);
        tlo += lo; thi += hi;
        if (i < b) { plo += lo; phi += hi; }
    }
    #pragma unroll
    for (int off = 16; off > 0; off >>= 1) {
        tlo += __shfl_down_sync(0xFFFFFFFFu, tlo, off);
        thi += __shfl_down_sync(0xFFFFFFFFu, thi, off);
        plo += __shfl_down_sync(0xFFFFFFFFu, plo, off);
        phi += __shfl_down_sync(0xFFFFFFFFu, phi, off);
    }
    if (lane == 0) {
        s_red[w][0] = tlo; s_red[w][1] = thi;
        s_red[w][2] = plo; s_red[w][3] = phi;
    }
    __syncthreads();

    if (t == 0) {
        unsigned long long a0 = 0, a1 = 0, a2 = 0, a3 = 0;
        #pragma unroll
        for (int i = 0; i < 8; i++) {
            a0 += s_red[i][0]; a1 += s_red[i][1];
            a2 += s_red[i][2]; a3 += s_red[i][3];
        }
        int cnt[E_EXP], ebase[E_EXP];
        #pragma unroll
        for (int e = 0; e < 4; e++) { cnt[e] = fld(a0, e); cnt[e + 4] = fld(a1, e); }
        int acc = 0;
        #pragma unroll
        for (int e = 0; e < E_EXP; e++) { ebase[e] = acc; acc += cnt[e]; }

        int run[E_EXP];
        #pragma unroll
        for (int e = 0; e < 4; e++) {
            run[e]     = ebase[e]     + fld(a2, e);
            run[e + 4] = ebase[e + 4] + fld(a3, e);
        }
        #pragma unroll
        for (int i = 0; i < TPB; i++) {
            const unsigned int mb = s_mask[i];
            int d0 = -1, d1 = -1;
            #pragma unroll
            for (int e = 0; e < E_EXP; e++) {
                if ((mb >> e) & 1u) {
                    if (d0 < 0) d0 = run[e]; else d1 = run[e];
                    run[e]++;
                }
            }
            s_dst[i] = make_int2(d0, d1);
        }
        if (b == 0) {
            #pragma unroll
            for (int e = 0; e < E_EXP; e++) out[CNT_OFF + e] = (float)cnt[e];
        }
    }
    __syncthreads();

    // ───── Phase 3: gather this block's 8 rows, write each twice ─────
    #pragma unroll
    for (int r = 0; r < TPB; r++) {
        const int n = b * TPB + r;
        const int2 d = s_dst[r];

        const float4* __restrict__ src = in_flow + (size_t)n * (DIM / 4);
        const float4 v0 = __ldg(src + t);
        const float4 v1 = __ldg(src + t + 256);

        float4* __restrict__ dst0 = out4 + (size_t)d.x * (DIM / 4);
        float4* __restrict__ dst1 = out4 + (size_t)d.y * (DIM / 4);
        __stcs(dst0 + t,       v0);
        __stcs(dst0 + t + 256, v1);
        __stcs(dst1 + t,       v0);
        __stcs(dst1 + t + 256, v1);

        if (t == 0) {
            out[TAGS_OFF + d.x] = (float)n;
            out[TAGS_OFF + d.y] = (float)n;
        }
    }
}

extern "C" void kernel_launch(void* const* d_in, const int* in_sizes, int n_in,
                              void* d_out, int out_size)
{
    const float* in_flow = (const float*)d_in[0];   // (8192, 2048) f32
    const float* gates   = (const float*)d_in[1];   // (8192, 8)    f32
    float* out = (float*)d_out;

    fused_kernel<<<NBLK, 256>>>((const float4*)gates, (const float4*)in_flow,
                                (float4*)out, out);
}

// round 15
// speedup vs baseline: 1.0475x; 1.0475x over previous
#include <cuda_runtime.h>

#define N_TOK   8192
#define E_EXP   8
#define DIM     2048
#define OUT_ROWS (N_TOK * 2)              // 16384
#define TAGS_OFF ((size_t)OUT_ROWS * DIM) // 33554432
#define CNT_OFF  (TAGS_OFF + OUT_ROWS)
#define NGRP    2048                      // 4-token groups
#define GPB     4                         // tokens per gather block

// scratch (no device allocs allowed)
__device__ unsigned char g_mask[N_TOK];   // top-2 mask per token
__device__ unsigned int  g_pcnt[NGRP];    // nibble-packed counts per 4-token group

// 4-bit fields -> 16-bit fields
__device__ __forceinline__ unsigned long long expand_lo(unsigned int p) {
    return (unsigned long long)(p & 0xF)
         | ((unsigned long long)((p >>  4) & 0xF) << 16)
         | ((unsigned long long)((p >>  8) & 0xF) << 32)
         | ((unsigned long long)((p >> 12) & 0xF) << 48);
}
__device__ __forceinline__ int fld(unsigned long long v, int e) {
    return (int)((v >> (16 * e)) & 0xFFFF);
}

// ── K1: masks + per-4-token-group nibble counts. No smem, no block sync. ───
__global__ __launch_bounds__(128) void route_kernel(const float4* __restrict__ gates4)
{
    const int n = blockIdx.x * 128 + threadIdx.x;
    const int lane = threadIdx.x & 31;

    const float4 a  = __ldg(gates4 + (size_t)n * 2);
    const float4 b4 = __ldg(gates4 + (size_t)n * 2 + 1);
    float g[E_EXP] = {a.x, a.y, a.z, a.w, b4.x, b4.y, b4.z, b4.w};

    int e1 = 0; float v1 = g[0];
    #pragma unroll
    for (int e = 1; e < E_EXP; e++) if (g[e] > v1) { v1 = g[e]; e1 = e; }
    int e2 = (e1 == 0) ? 1 : 0; float v2 = g[e2];
    #pragma unroll
    for (int e = 0; e < E_EXP; e++)
        if (e != e1 && g[e] > v2) { v2 = g[e]; e2 = e; }
    const unsigned int mb = (1u << e1) | (1u << e2);
    g_mask[n] = (unsigned char)mb;

    // nibble-pack: one 4-bit field per expert; reduce across the 4-lane quad
    unsigned int pack = 0;
    #pragma unroll
    for (int e = 0; e < E_EXP; e++) pack |= ((mb >> e) & 1u) << (4 * e);
    pack += __shfl_down_sync(0xFFFFFFFFu, pack, 2);
    pack += __shfl_down_sync(0xFFFFFFFFu, pack, 1);
    if ((lane & 3) == 0) g_pcnt[n >> 2] = pack;   // per-expert count <= 4, fits
}

// ── K2: gather, each block handles 4 tokens; prefix computed in-block and
//    hidden behind the row loads issued first. ─────────────────────────────
__global__ __launch_bounds__(256) void gather_kernel(
    const float4* __restrict__ in_flow, float4* __restrict__ out4,
    float* __restrict__ out)
{
    __shared__ unsigned long long s_red[8][4];
    __shared__ int2 s_dst[GPB];

    const int b = blockIdx.x;
    const int t = threadIdx.x;
    const int lane = t & 31, w = t >> 5;
    const int n0 = b * GPB;

    // ── issue first-half row loads immediately (prologue hides under these) ─
    const float4* __restrict__ src0 = in_flow + (size_t)(n0 + 0) * (DIM / 4);
    const float4* __restrict__ src1 = in_flow + (size_t)(n0 + 1) * (DIM / 4);
    const float4 v00 = __ldg(src0 + t);
    const float4 v01 = __ldg(src0 + t + 256);
    const float4 v10 = __ldg(src1 + t);
    const float4 v11 = __ldg(src1 + t + 256);

    // ── prologue: totals + prefix over earlier groups (8KB coalesced) ──────
    unsigned long long tlo = 0ull, thi = 0ull, plo = 0ull, phi = 0ull;
    #pragma unroll
    for (int j = 0; j < NGRP / 256; j++) {
        const int i = t + 256 * j;
        const unsigned int p = g_pcnt[i];
        const unsigned long long lo = expand_lo(p);
        const unsigned long long hi = expand_lo(p >> 16);
        tlo += lo; thi += hi;
        if (i < b) { plo += lo; phi += hi; }
    }
    #pragma unroll
    for (int off = 16; off > 0; off >>= 1) {
        tlo += __shfl_down_sync(0xFFFFFFFFu, tlo, off);
        thi += __shfl_down_sync(0xFFFFFFFFu, thi, off);
        plo += __shfl_down_sync(0xFFFFFFFFu, plo, off);
        phi += __shfl_down_sync(0xFFFFFFFFu, phi, off);
    }
    if (lane == 0) {
        s_red[w][0] = tlo; s_red[w][1] = thi;
        s_red[w][2] = plo; s_red[w][3] = phi;
    }
    __syncthreads();

    if (t == 0) {
        unsigned long long a0 = 0, a1 = 0, a2 = 0, a3 = 0;
        #pragma unroll
        for (int i = 0; i < 8; i++) {
            a0 += s_red[i][0]; a1 += s_red[i][1];
            a2 += s_red[i][2]; a3 += s_red[i][3];
        }
        int cnt[E_EXP], ebase[E_EXP];
        #pragma unroll
        for (int e = 0; e < 4; e++) { cnt[e] = fld(a0, e); cnt[e + 4] = fld(a1, e); }
        int acc = 0;
        #pragma unroll
        for (int e = 0; e < E_EXP; e++) { ebase[e] = acc; acc += cnt[e]; }

        int run[E_EXP];
        #pragma unroll
        for (int e = 0; e < 4; e++) {
            run[e]     = ebase[e]     + fld(a2, e);
            run[e + 4] = ebase[e + 4] + fld(a3, e);
        }
        const unsigned int um = ((const unsigned int*)g_mask)[b]; // 4 masks
        #pragma unroll
        for (int i = 0; i < GPB; i++) {
            const unsigned int mb = (um >> (8 * i)) & 0xFFu;
            int d0 = -1, d1 = -1;
            #pragma unroll
            for (int e = 0; e < E_EXP; e++) {
                if ((mb >> e) & 1u) {
                    if (d0 < 0) d0 = run[e]; else d1 = run[e];
                    run[e]++;
                }
            }
            s_dst[i] = make_int2(d0, d1);
        }
        if (b == 0) {
            #pragma unroll
            for (int e = 0; e < E_EXP; e++) out[CNT_OFF + e] = (float)cnt[e];
        }
    }
    __syncthreads();

    // ── store rows 0,1 (already in registers) ──────────────────────────────
    {
        const int2 d0 = s_dst[0], d1 = s_dst[1];
        float4* __restrict__ a0 = out4 + (size_t)d0.x * (DIM / 4);
        float4* __restrict__ a1 = out4 + (size_t)d0.y * (DIM / 4);
        float4* __restrict__ b0 = out4 + (size_t)d1.x * (DIM / 4);
        float4* __restrict__ b1 = out4 + (size_t)d1.y * (DIM / 4);
        __stcs(a0 + t,       v00); __stcs(a0 + t + 256, v01);
        __stcs(a1 + t,       v00); __stcs(a1 + t + 256, v01);
        __stcs(b0 + t,       v10); __stcs(b0 + t + 256, v11);
        __stcs(b1 + t,       v10); __stcs(b1 + t + 256, v11);
    }

    // ── rows 2,3 ───────────────────────────────────────────────────────────
    {
        const float4* __restrict__ src2 = in_flow + (size_t)(n0 + 2) * (DIM / 4);
        const float4* __restrict__ src3 = in_flow + (size_t)(n0 + 3) * (DIM / 4);
        const float4 v20 = __ldg(src2 + t);
        const float4 v21 = __ldg(src2 + t + 256);
        const float4 v30 = __ldg(src3 + t);
        const float4 v31 = __ldg(src3 + t + 256);

        const int2 d2 = s_dst[2], d3 = s_dst[3];
        float4* __restrict__ a0 = out4 + (size_t)d2.x * (DIM / 4);
        float4* __restrict__ a1 = out4 + (size_t)d2.y * (DIM / 4);
        float4* __restrict__ b0 = out4 + (size_t)d3.x * (DIM / 4);
        float4* __restrict__ b1 = out4 + (size_t)d3.y * (DIM / 4);
        __stcs(a0 + t,       v20); __stcs(a0 + t + 256, v21);
        __stcs(a1 + t,       v20); __stcs(a1 + t + 256, v21);
        __stcs(b0 + t,       v30); __stcs(b0 + t + 256, v31);
        __stcs(b1 + t,       v30); __stcs(b1 + t + 256, v31);
    }

    // tags: one 4B store per (row, copy), spread over threads 0..3
    if (t < GPB) {
        const int2 d = s_dst[t];
        const float tag = (float)(n0 + t);
        out[TAGS_OFF + d.x] = tag;
        out[TAGS_OFF + d.y] = tag;
    }
}

extern "C" void kernel_launch(void* const* d_in, const int* in_sizes, int n_in,
                              void* d_out, int out_size)
{
    const float* in_flow = (const float*)d_in[0];   // (8192, 2048) f32
    const float* gates   = (const float*)d_in[1];   // (8192, 8)    f32
    float* out = (float*)d_out;

    route_kernel<<<N_TOK / 128, 128>>>((const float4*)gates);
    gather_kernel<<<NGRP, 256>>>((const float4*)in_flow, (float4*)out, out);
}

// round 16
// speedup vs baseline: 1.0556x; 1.0077x over previous
#include <cuda_runtime.h>

#define N_TOK   8192
#define E_EXP   8
#define DIM     2048
#define OUT_ROWS (N_TOK * 2)              // 16384
#define TAGS_OFF ((size_t)OUT_ROWS * DIM) // 33554432
#define CNT_OFF  (TAGS_OFF + OUT_ROWS)
#define NBLK    32                        // routing blocks (256 tokens each)

// scratch (no device allocs allowed)
__device__ unsigned long long g_bcnt_lo[NBLK];
__device__ unsigned long long g_bcnt_hi[NBLK];
__device__ int2               g_dst[N_TOK];
__device__ unsigned int       g_sync;     // monotonic ticket barrier (replay-safe)

__device__ __forceinline__ unsigned long long spread4(unsigned int m4) {
    return (unsigned long long)(m4 & 1)
         | ((unsigned long long)((m4 >> 1) & 1) << 16)
         | ((unsigned long long)((m4 >> 2) & 1) << 32)
         | ((unsigned long long)((m4 >> 3) & 1) << 48);
}
__device__ __forceinline__ int fld(unsigned long long v, int e) {
    return (int)((v >> (16 * e)) & 0xFFFF);
}

// ── K1: fused routing (32 blocks, ticket barrier). Also writes tags+counts. ─
__global__ __launch_bounds__(256) void route_kernel(
    const float4* __restrict__ gates4, float* __restrict__ out)
{
    __shared__ unsigned long long sw_lo[8], sw_hi[8];

    const int b = blockIdx.x;
    const int t = threadIdx.x;
    const int n = b * 256 + t;
    const int lane = t & 31, w = t >> 5;

    // ---- top-2 mask ----
    const float4 a   = __ldg(gates4 + (size_t)n * 2);
    const float4 bb4 = __ldg(gates4 + (size_t)n * 2 + 1);
    float g[E_EXP] = {a.x, a.y, a.z, a.w, bb4.x, bb4.y, bb4.z, bb4.w};

    int e1 = 0; float v1 = g[0];
    #pragma unroll
    for (int e = 1; e < E_EXP; e++) if (g[e] > v1) { v1 = g[e]; e1 = e; }
    int e2 = (e1 == 0) ? 1 : 0; float v2 = g[e2];
    #pragma unroll
    for (int e = 0; e < E_EXP; e++)
        if (e != e1 && g[e] > v2) { v2 = g[e]; e2 = e; }
    const unsigned int mb = (1u << e1) | (1u << e2);

    const unsigned long long lo = spread4(mb & 0xF);
    const unsigned long long hi = spread4(mb >> 4);

    // ---- warp inclusive scan ----
    unsigned long long slo = lo, shi = hi;
    #pragma unroll
    for (int off = 1; off < 32; off <<= 1) {
        unsigned long long al = __shfl_up_sync(0xFFFFFFFFu, slo, off);
        unsigned long long ah = __shfl_up_sync(0xFFFFFFFFu, shi, off);
        if (lane >= off) { slo += al; shi += ah; }
    }
    if (lane == 31) { sw_lo[w] = slo; sw_hi[w] = shi; }
    __syncthreads();

    if (t == 0) {
        unsigned long long tl = 0ull, th = 0ull;
        #pragma unroll
        for (int i = 0; i < 8; i++) { tl += sw_lo[i]; th += sw_hi[i]; }
        g_bcnt_lo[b] = tl;
        g_bcnt_hi[b] = th;
    }

    // ---- device-wide ticket barrier ----
    __syncthreads();
    if (t == 0) {
        __threadfence();
        const unsigned int ticket = atomicAdd(&g_sync, 1u);
        const unsigned int target = (ticket / NBLK + 1u) * NBLK;
        volatile unsigned int* sy = &g_sync;
        while (*sy < target) { }
        __threadfence();
    }
    __syncthreads();

    // ---- global totals + prefix over earlier blocks (coherent L2 reads) ---
    unsigned long long blo = 0ull, bhi = 0ull, tlo = 0ull, thi = 0ull;
    #pragma unroll
    for (int i = 0; i < NBLK; i++) {
        const unsigned long long l = __ldcg(&g_bcnt_lo[i]);
        const unsigned long long h = __ldcg(&g_bcnt_hi[i]);
        if (i < b) { blo += l; bhi += h; }
        tlo += l; thi += h;
    }

    int cnt[E_EXP], ebase[E_EXP];
    #pragma unroll
    for (int e = 0; e < 4; e++) { cnt[e] = fld(tlo, e); cnt[e + 4] = fld(thi, e); }
    int acc = 0;
    #pragma unroll
    for (int e = 0; e < E_EXP; e++) { ebase[e] = acc; acc += cnt[e]; }

    // in-block exclusive prefix for this thread
    unsigned long long plo = 0ull, phi = 0ull;
    #pragma unroll
    for (int i = 0; i < 8; i++) if (i < w) { plo += sw_lo[i]; phi += sw_hi[i]; }
    const unsigned long long ex_lo = plo + slo - lo;
    const unsigned long long ex_hi = phi + shi - hi;

    int dsts[2]; int k = 0;
    #pragma unroll
    for (int e = 0; e < E_EXP; e++) {
        if ((mb >> e) & 1u) {
            const int pre = (e < 4) ? fld(blo, e) : fld(bhi, e - 4);
            const int loc = (e < 4) ? fld(ex_lo, e) : fld(ex_hi, e - 4);
            dsts[k & 1] = ebase[e] + pre + loc;
            k++;
        }
    }
    g_dst[n] = make_int2(dsts[0], dsts[1]);

    // tags written here (gather stays pure copy)
    const float tag = (float)n;
    out[TAGS_OFF + dsts[0]] = tag;
    out[TAGS_OFF + dsts[1]] = tag;

    if (b == 0 && t == 0) {
        #pragma unroll
        for (int e = 0; e < E_EXP; e++) out[CNT_OFF + e] = (float)cnt[e];
    }
}

// ── K2: pure gather — read row once (streaming), write twice (streaming) ───
__global__ __launch_bounds__(256) void gather_kernel(
    const float4* __restrict__ in_flow, float4* __restrict__ out4)
{
    const int n = blockIdx.x;
    const int2 d = g_dst[n];
    const int t = threadIdx.x;

    const float4* __restrict__ src = in_flow + (size_t)n * (DIM / 4);
    const float4 v0 = __ldcs(src + t);
    const float4 v1 = __ldcs(src + t + 256);

    float4* __restrict__ dst0 = out4 + (size_t)d.x * (DIM / 4);
    float4* __restrict__ dst1 = out4 + (size_t)d.y * (DIM / 4);
    __stcs(dst0 + t,       v0);
    __stcs(dst0 + t + 256, v1);
    __stcs(dst1 + t,       v0);
    __stcs(dst1 + t + 256, v1);
}

extern "C" void kernel_launch(void* const* d_in, const int* in_sizes, int n_in,
                              void* d_out, int out_size)
{
    const float* in_flow = (const float*)d_in[0];   // (8192, 2048) f32
    const float* gates   = (const float*)d_in[1];   // (8192, 8)    f32
    float* out = (float*)d_out;

    route_kernel<<<NBLK, 256>>>((const float4*)gates, out);
    gather_kernel<<<N_TOK, 256>>>((const float4*)in_flow, (float4*)out);
}

// round 17
// speedup vs baseline: 1.1078x; 1.0494x over previous
#include <cuda_runtime.h>

#define N_TOK   8192
#define E_EXP   8
#define DIM     2048
#define OUT_ROWS (N_TOK * 2)              // 16384
#define TAGS_OFF ((size_t)OUT_ROWS * DIM) // 33554432
#define CNT_OFF  (TAGS_OFF + OUT_ROWS)
#define NBLK    32                        // routing blocks (256 tokens each)

// scratch (no device allocs allowed)
__device__ unsigned long long g_bcnt_lo[NBLK];
__device__ unsigned long long g_bcnt_hi[NBLK];
__device__ int2               g_dst[N_TOK];
__device__ unsigned int       g_sync;     // monotonic ticket barrier (replay-safe)

__device__ __forceinline__ unsigned long long spread4(unsigned int m4) {
    return (unsigned long long)(m4 & 1)
         | ((unsigned long long)((m4 >> 1) & 1) << 16)
         | ((unsigned long long)((m4 >> 2) & 1) << 32)
         | ((unsigned long long)((m4 >> 3) & 1) << 48);
}
__device__ __forceinline__ int fld(unsigned long long v, int e) {
    return (int)((v >> (16 * e)) & 0xFFFF);
}

// ── K1: fused routing (32 blocks, ticket barrier). Writes g_dst, tags, counts.
//    Triggers the dependent gather launch immediately on entry. ─────────────
__global__ __launch_bounds__(256) void route_kernel(
    const float4* __restrict__ gates4, float* __restrict__ out)
{
    __shared__ unsigned long long sw_lo[8], sw_hi[8];

    // let the gather kernel's prologue start right away
    cudaTriggerProgrammaticLaunchCompletion();

    const int b = blockIdx.x;
    const int t = threadIdx.x;
    const int n = b * 256 + t;
    const int lane = t & 31, w = t >> 5;

    // ---- top-2 mask ----
    const float4 a   = __ldg(gates4 + (size_t)n * 2);
    const float4 bb4 = __ldg(gates4 + (size_t)n * 2 + 1);
    float g[E_EXP] = {a.x, a.y, a.z, a.w, bb4.x, bb4.y, bb4.z, bb4.w};

    int e1 = 0; float v1 = g[0];
    #pragma unroll
    for (int e = 1; e < E_EXP; e++) if (g[e] > v1) { v1 = g[e]; e1 = e; }
    int e2 = (e1 == 0) ? 1 : 0; float v2 = g[e2];
    #pragma unroll
    for (int e = 0; e < E_EXP; e++)
        if (e != e1 && g[e] > v2) { v2 = g[e]; e2 = e; }
    const unsigned int mb = (1u << e1) | (1u << e2);

    const unsigned long long lo = spread4(mb & 0xF);
    const unsigned long long hi = spread4(mb >> 4);

    // ---- warp inclusive scan ----
    unsigned long long slo = lo, shi = hi;
    #pragma unroll
    for (int off = 1; off < 32; off <<= 1) {
        unsigned long long al = __shfl_up_sync(0xFFFFFFFFu, slo, off);
        unsigned long long ah = __shfl_up_sync(0xFFFFFFFFu, shi, off);
        if (lane >= off) { slo += al; shi += ah; }
    }
    if (lane == 31) { sw_lo[w] = slo; sw_hi[w] = shi; }
    __syncthreads();

    if (t == 0) {
        unsigned long long tl = 0ull, th = 0ull;
        #pragma unroll
        for (int i = 0; i < 8; i++) { tl += sw_lo[i]; th += sw_hi[i]; }
        g_bcnt_lo[b] = tl;
        g_bcnt_hi[b] = th;
    }

    // ---- device-wide ticket barrier ----
    __syncthreads();
    if (t == 0) {
        __threadfence();
        const unsigned int ticket = atomicAdd(&g_sync, 1u);
        const unsigned int target = (ticket / NBLK + 1u) * NBLK;
        volatile unsigned int* sy = &g_sync;
        while (*sy < target) { }
        __threadfence();
    }
    __syncthreads();

    // ---- global totals + prefix over earlier blocks (coherent L2 reads) ---
    unsigned long long blo = 0ull, bhi = 0ull, tlo = 0ull, thi = 0ull;
    #pragma unroll
    for (int i = 0; i < NBLK; i++) {
        const unsigned long long l = __ldcg(&g_bcnt_lo[i]);
        const unsigned long long h = __ldcg(&g_bcnt_hi[i]);
        if (i < b) { blo += l; bhi += h; }
        tlo += l; thi += h;
    }

    int cnt[E_EXP], ebase[E_EXP];
    #pragma unroll
    for (int e = 0; e < 4; e++) { cnt[e] = fld(tlo, e); cnt[e + 4] = fld(thi, e); }
    int acc = 0;
    #pragma unroll
    for (int e = 0; e < E_EXP; e++) { ebase[e] = acc; acc += cnt[e]; }

    unsigned long long plo = 0ull, phi = 0ull;
    #pragma unroll
    for (int i = 0; i < 8; i++) if (i < w) { plo += sw_lo[i]; phi += sw_hi[i]; }
    const unsigned long long ex_lo = plo + slo - lo;
    const unsigned long long ex_hi = phi + shi - hi;

    int dsts[2]; int k = 0;
    #pragma unroll
    for (int e = 0; e < E_EXP; e++) {
        if ((mb >> e) & 1u) {
            const int pre = (e < 4) ? fld(blo, e) : fld(bhi, e - 4);
            const int loc = (e < 4) ? fld(ex_lo, e) : fld(ex_hi, e - 4);
            dsts[k & 1] = ebase[e] + pre + loc;
            k++;
        }
    }
    g_dst[n] = make_int2(dsts[0], dsts[1]);

    const float tag = (float)n;
    out[TAGS_OFF + dsts[0]] = tag;
    out[TAGS_OFF + dsts[1]] = tag;

    if (b == 0 && t == 0) {
        #pragma unroll
        for (int e = 0; e < E_EXP; e++) out[CNT_OFF + e] = (float)cnt[e];
    }
}

// ── K2: pure gather with PDL prologue — issue row loads BEFORE the grid
//    dependency sync so they overlap the route kernel. ─────────────────────
__global__ __launch_bounds__(256) void gather_kernel(
    const float4* __restrict__ in_flow, float4* __restrict__ out4)
{
    const int n = blockIdx.x;
    const int t = threadIdx.x;

    // prologue: loads in flight while route finishes
    const float4* __restrict__ src = in_flow + (size_t)n * (DIM / 4);
    const float4 v0 = __ldcs(src + t);
    const float4 v1 = __ldcs(src + t + 256);

    // wait until route's writes (g_dst) are visible
    cudaGridDependencySynchronize();

    const int2 d = g_dst[n];
    float4* __restrict__ dst0 = out4 + (size_t)d.x * (DIM / 4);
    float4* __restrict__ dst1 = out4 + (size_t)d.y * (DIM / 4);
    __stcs(dst0 + t,       v0);
    __stcs(dst0 + t + 256, v1);
    __stcs(dst1 + t,       v0);
    __stcs(dst1 + t + 256, v1);
}

extern "C" void kernel_launch(void* const* d_in, const int* in_sizes, int n_in,
                              void* d_out, int out_size)
{
    const float* in_flow = (const float*)d_in[0];   // (8192, 2048) f32
    const float* gates   = (const float*)d_in[1];   // (8192, 8)    f32
    float* out = (float*)d_out;

    route_kernel<<<NBLK, 256>>>((const float4*)gates, out);

    // gather with programmatic dependent launch (overlaps route)
    cudaLaunchConfig_t cfg = {};
    cfg.gridDim  = dim3(N_TOK);
    cfg.blockDim = dim3(256);
    cfg.dynamicSmemBytes = 0;
    cfg.stream = 0;
    cudaLaunchAttribute attr[1];
    attr[0].id = cudaLaunchAttributeProgrammaticStreamSerialization;
    attr[0].val.programmaticStreamSerializationAllowed = 1;
    cfg.attrs = attr;
    cfg.numAttrs = 1;
    const float4* arg0 = (const float4*)in_flow;
    float4* arg1 = (float4*)out;
    cudaLaunchKernelEx(&cfg, gather_kernel, arg0, arg1);
}